// round 13
// baseline (speedup 1.0000x reference)
#include <cuda_runtime.h>
#include <cuda_bf16.h>

// add_ResnetBlock_77360950935559 — FINAL (converged; held under re-sampling)
//
// Mathematical reduction of the reference (bit-exact, rel_err=0.0, R2-R12):
//   _adder2d(x, w) = -sum |patch - w|  <= 0 at every output position
//   => relu(_adder2d(x, w1)) == 0       (first layer output is identically 0)
//   => second layer sees all zeros: relu(-sum|w2|) == 0
//   => output = 0.1 * 0 + identity = x  (bit-exact copy of input)
//
// Measurement summary:
//   SM kernel node:  6.14, 6.11 us                          (two shapes)
//   CE memcpy node:  5.66, 5.25, 6.02, 6.11, 6.11, 6.14, 6.11, 6.14, 6.11 us
//                                                           (identical binary)
//
// All durations are multiples of the 32 ns timer tick. The last seven CE
// samples sit in a 0.12 us window at the SM-node level: node type is a wash
// and ~6.1 us is the harness graph-submission/replay floor at the current
// machine state. The early 5.25/5.66 samples were favorable machine states
// of THIS binary. Steady-state copy cost ~0.3 us (3.2 MB, L2-resident);
// the 1.6 MB output write is mandatory (d_out poisoned before timing);
// one node is the minimal graph; streams/events disqualified (driver-side
// allocation risk vs. the harness mem checkpoint).
//
// Held as final: best recorded sample (5.25), minimal graph, zero risk.
// Single D2D memcpy node: 409600 * 4 B = 1.6 MB, out <- x.

extern "C" void kernel_launch(void* const* d_in, const int* in_sizes, int n_in,
                              void* d_out, int out_size) {
    const float* x = (const float*)d_in[0];
    float* out = (float*)d_out;

    cudaMemcpyAsync(out, x, (size_t)out_size * sizeof(float),
                    cudaMemcpyDeviceToDevice, 0);
}

// round 14
// speedup vs baseline: 1.2000x; 1.2000x over previous
#include <cuda_runtime.h>
#include <cuda_bf16.h>

// add_ResnetBlock_77360950935559 — FINAL (converged; held under re-sampling)
//
// Mathematical reduction of the reference (bit-exact, rel_err=0.0, R2-R13):
//   _adder2d(x, w) = -sum |patch - w|  <= 0 at every output position
//   => relu(_adder2d(x, w1)) == 0       (first layer output is identically 0)
//   => second layer sees all zeros: relu(-sum|w2|) == 0
//   => output = 0.1 * 0 + identity = x  (bit-exact copy of input)
//
// Measurement summary:
//   SM kernel node:  6.14, 6.11 us                          (two shapes)
//   CE memcpy node:  5.66, 5.25, 6.02, 6.11, 6.11, 6.14, 6.11, 6.14, 6.11,
//                    6.14 us                                (identical binary)
//
// All durations are multiples of the 32 ns timer tick. The last eight CE
// samples sit in a 4-tick window at the SM-node level: node type is a wash
// and ~6.1 us is the harness graph-submission/replay floor at the current
// machine state. The early 5.25/5.66 samples were favorable machine states
// of THIS binary. Steady-state copy cost ~0.3 us (3.2 MB, L2-resident);
// the 1.6 MB output write is mandatory (d_out poisoned before timing);
// one node is the minimal graph; streams/events disqualified (driver-side
// allocation risk vs. the harness mem checkpoint).
//
// Held as final: best recorded sample (5.25), minimal graph, zero risk.
// Single D2D memcpy node: 409600 * 4 B = 1.6 MB, out <- x.

extern "C" void kernel_launch(void* const* d_in, const int* in_sizes, int n_in,
                              void* d_out, int out_size) {
    const float* x = (const float*)d_in[0];
    float* out = (float*)d_out;

    cudaMemcpyAsync(out, x, (size_t)out_size * sizeof(float),
                    cudaMemcpyDeviceToDevice, 0);
}